// round 8
// baseline (speedup 1.0000x reference)
#include <cuda_runtime.h>
#include <cuda_bf16.h>
#include <cstdint>

// Locally-connected 2D via mma.sync m16n8k16 bf16, 3-pass hi/lo split.
//   out[b,o,y,x] = sum_k patches[b,y,x,k] * W[y,x,o,k] + bias[y,x,o]
// x: [128,3,64,64] f32, W: [60,60,32,75] f32 (k = c*25+kh*5+kw),
// bias: [60,60,32] f32, out: [128,32,60,60] f32.
// CTA = (y, 10 x-positions): D[128x32] = A[128x75] @ B[75x32] per position.
// W pre-split into per-warp-coalesced HMMA fragment images (g_wfragB, LDG'd
// directly, no smem). x pre-packed (bf16hi<<16|bf16lo). Output stored as
// 40B px-runs (float2) after an in-smem repack.

#define RYX  60
#define TX   10
#define XC   14          // TX + 4
#define NROW 210         // 15 * XC
#define SXB  132         // sXp row stride (u32)
#define NTHR 640

#define XP_BYTES   (NROW * SXB * 4)        // 110880
#define SREP_BYTES 182784                  // >= (127*357 + 31*11 + 9 + 1)*4
#define BIAS_OFF   SREP_BYTES
#define SMEM_TOTAL (BIAS_OFF + TX * 32 * 4)   // 184064

__device__ unsigned g_xp[3 * 64 * 64 * 128];   // packed x (bf16hi<<16|bf16lo), b fast
__device__ uint2    g_wfragB[3600 * 1280];     // [pos][s:5][a:2][nt:4][gid:8][tg:4]

// ---------------------------------------------------------------- helpers
__device__ __forceinline__ unsigned smem_u32(const void* p) {
    unsigned a;
    asm("{ .reg .u64 t; cvta.to.shared.u64 t, %1; cvt.u32.u64 %0, t; }" : "=r"(a) : "l"(p));
    return a;
}
__device__ __forceinline__ void cp16(unsigned sm, const void* g) {
    asm volatile("cp.async.cg.shared.global [%0], [%1], 16;"
                 :: "r"(sm), "l"(__cvta_generic_to_global(g)) : "memory");
}
__device__ __forceinline__ void cp_commit_wait() {
    asm volatile("cp.async.commit_group;" ::: "memory");
    asm volatile("cp.async.wait_group 0;" ::: "memory");
}
__device__ __forceinline__ int rcof(int k) {       // sXp row for flat k (pos 0)
    int c = k / 25, r = (k % 25) / 5, w = k % 5;
    return (c * 5 + r) * XC + w;
}
__device__ __forceinline__ void mma_bf16(float* d, const unsigned* a, unsigned b0, unsigned b1) {
    asm volatile(
        "mma.sync.aligned.m16n8k16.row.col.f32.bf16.bf16.f32 "
        "{%0,%1,%2,%3}, {%4,%5,%6,%7}, {%8,%9}, {%0,%1,%2,%3};"
        : "+f"(d[0]), "+f"(d[1]), "+f"(d[2]), "+f"(d[3])
        : "r"(a[0]), "r"(a[1]), "r"(a[2]), "r"(a[3]), "r"(b0), "r"(b1));
}

// ---------------------------------------------------------------- prep: pack x
__global__ __launch_bounds__(256)
void prep_x_kernel(const float* __restrict__ x)
{
    __shared__ unsigned tile[32][33];
    const int wt    = blockIdx.x & 1;
    const int btile = blockIdx.x >> 1;
    const int h     = blockIdx.y;
    const int c     = blockIdx.z;
    const int tx = threadIdx.x, ty = threadIdx.y;

    #pragma unroll
    for (int j = 0; j < 4; j++) {
        int b = btile * 32 + ty + j * 8;
        float v = x[(((size_t)b * 3 + c) * 64 + h) * 64 + wt * 32 + tx];
        __nv_bfloat16 hi = __float2bfloat16_rn(v);
        __nv_bfloat16 lo = __float2bfloat16_rn(v - __bfloat162float(hi));
        tile[ty + j * 8][tx] = ((unsigned)__bfloat16_as_ushort(hi) << 16)
                             |  (unsigned)__bfloat16_as_ushort(lo);
    }
    __syncthreads();
    #pragma unroll
    for (int j = 0; j < 4; j++) {
        int w = wt * 32 + ty + j * 8;
        g_xp[(((size_t)c * 64 + h) * 64 + w) * 128 + btile * 32 + tx] = tile[tx][ty + j * 8];
    }
}

// ---------------------------------------------------------------- prep: split W into B-fragment images
// uint2 at [pos][s][a][nt][gid][tg]:
//   o = nt*8 + gid, k0 = 16*s + 2*tg
//   .x = bf16(W[o,k0])   | bf16(W[o,k0+1]) << 16
//   .y = bf16(W[o,k0+8]) | bf16(W[o,k0+9]) << 16    (zero-padded k >= 75)
// a=0: hi split, a=1: lo split.
__global__ __launch_bounds__(256)
void prep_w_kernel(const float* __restrict__ W)
{
    const int pos = blockIdx.x;
    const float* Wg = W + (size_t)pos * (32 * 75);
    uint2* dst = g_wfragB + (size_t)pos * 1280;

    for (int i = threadIdx.x; i < 1280; i += 256) {
        int tg  = i & 3;
        int gid = (i >> 2) & 7;
        int nt  = (i >> 5) & 3;
        int a   = (i >> 7) & 1;
        int s   = i >> 8;
        int o   = nt * 8 + gid;
        int k0  = 16 * s + 2 * tg;

        float v[4];
        v[0] = (k0     < 75) ? Wg[o * 75 + k0]     : 0.0f;
        v[1] = (k0 + 1 < 75) ? Wg[o * 75 + k0 + 1] : 0.0f;
        v[2] = (k0 + 8 < 75) ? Wg[o * 75 + k0 + 8] : 0.0f;
        v[3] = (k0 + 9 < 75) ? Wg[o * 75 + k0 + 9] : 0.0f;

        unsigned r[4];
        #pragma unroll
        for (int j = 0; j < 4; j++) {
            unsigned wb = __float_as_uint(v[j]);
            if (a == 0) {
                r[j] = wb >> 16;
            } else {
                float lo = v[j] - __uint_as_float(wb & 0xFFFF0000u);
                r[j] = (unsigned)__bfloat16_as_ushort(__float2bfloat16_rn(lo));
            }
        }
        dst[i] = make_uint2(r[0] | (r[1] << 16), r[2] | (r[3] << 16));
    }
}

// ---------------------------------------------------------------- main
__global__ __launch_bounds__(NTHR, 1)
void lc2d_hmma_kernel(const float* __restrict__ bias,
                      float* __restrict__ out)
{
    extern __shared__ char smem[];
    unsigned* sXp   = (unsigned*)smem;              // [NROW][SXB] packed u32
    float*    sRep  = (float*)smem;                 // overlay after compute
    float*    sBias = (float*)(smem + BIAS_OFF);    // [TX][32]

    const int xt   = blockIdx.x;          // 6
    const int py   = blockIdx.y;          // 60
    const int px0  = xt * TX;
    const int pos0 = py * RYX + px0;
    const int tid  = threadIdx.x;

    const unsigned sXp_a = smem_u32(sXp);

    // ---- stage x tile: cp.async uint4, coalesced ----
    for (int i = tid; i < NROW * 32; i += NTHR) {
        int q    = i & 31;
        int rc   = i >> 5;                 // (c*5+kh)*XC + col
        int crow = rc / XC, col = rc - crow * XC;
        int c = crow / 5, kh = crow - c * 5;
        cp16(sXp_a + (rc * SXB + q * 4) * 4,
             &g_xp[(((size_t)c * 64 + py + kh) * 64 + px0 + col) * 128 + q * 4]);
    }
    if (tid < TX * 32) sBias[tid] = bias[pos0 * 32 + tid];
    cp_commit_wait();
    __syncthreads();

    // ---- compute: warp = (position p, m-half mh); 4 m-tiles x 4 n-tiles ----
    const int wid  = tid >> 5;
    const int lane = tid & 31;
    const int gid  = lane >> 2;
    const int tg   = lane & 3;
    const int p    = wid >> 1;          // 0..9
    const int mh   = wid & 1;

    float acc[4][4][4];
    #pragma unroll
    for (int mt = 0; mt < 4; mt++)
        #pragma unroll
        for (int nt = 0; nt < 4; nt++)
            #pragma unroll
            for (int r = 0; r < 4; r++) acc[mt][nt][r] = 0.0f;

    // per-lane B-fragment pointer (coalesced: 32 lanes -> 256B)
    const uint2* wfp = g_wfragB + (size_t)(pos0 + p) * 1280 + gid * 4 + tg;

    #pragma unroll
    for (int s = 0; s < 5; s++) {
        uint2 bh[4], bl[4];
        #pragma unroll
        for (int nt = 0; nt < 4; nt++) {
            bh[nt] = __ldg(wfp + s * 256 + nt * 32);          // hi
            bl[nt] = __ldg(wfp + s * 256 + 128 + nt * 32);    // lo
        }

        // A row offsets for k0, k0+1, k0+8, k0+9
        const int k0 = 16 * s + 2 * tg;
        int off0, off1, off2, off3;
        bool v2 = true, v3 = true;
        if (s < 4) {
            off0 = (rcof(k0)     + p) * SXB;
            off1 = (rcof(k0 + 1) + p) * SXB;
            off2 = (rcof(k0 + 8) + p) * SXB;
            off3 = (rcof(k0 + 9) + p) * SXB;
        } else {
            off0 = (rcof(k0)     + p) * SXB;
            off1 = (rcof(k0 + 1) + p) * SXB;
            v2 = (k0 + 8) < 75;  off2 = v2 ? (rcof(k0 + 8) + p) * SXB : 0;
            v3 = (k0 + 9) < 75;  off3 = v3 ? (rcof(k0 + 9) + p) * SXB : 0;
        }

        #pragma unroll
        for (int mt = 0; mt < 4; mt++) {
            const int b = mh * 64 + mt * 16 + gid;
            unsigned x0 = sXp[off0 + b];
            unsigned x1 = sXp[off1 + b];
            unsigned x2 = sXp[off0 + b + 8];
            unsigned x3 = sXp[off1 + b + 8];
            unsigned x4 = v2 ? sXp[off2 + b]     : 0u;
            unsigned x5 = v3 ? sXp[off3 + b]     : 0u;
            unsigned x6 = v2 ? sXp[off2 + b + 8] : 0u;
            unsigned x7 = v3 ? sXp[off3 + b + 8] : 0u;

            unsigned ah[4], al[4];
            ah[0] = __byte_perm(x0, x1, 0x7632);  al[0] = __byte_perm(x0, x1, 0x5410);
            ah[1] = __byte_perm(x2, x3, 0x7632);  al[1] = __byte_perm(x2, x3, 0x5410);
            ah[2] = __byte_perm(x4, x5, 0x7632);  al[2] = __byte_perm(x4, x5, 0x5410);
            ah[3] = __byte_perm(x6, x7, 0x7632);  al[3] = __byte_perm(x6, x7, 0x5410);

            #pragma unroll
            for (int nt = 0; nt < 4; nt++)
                mma_bf16(acc[mt][nt], ah, bh[nt].x, bh[nt].y);   // hi*hi
            #pragma unroll
            for (int nt = 0; nt < 4; nt++)
                mma_bf16(acc[mt][nt], ah, bl[nt].x, bl[nt].y);   // hi*lo
            #pragma unroll
            for (int nt = 0; nt < 4; nt++)
                mma_bf16(acc[mt][nt], al, bh[nt].x, bh[nt].y);   // lo*hi
        }
    }

    // ---- bias (into regs before smem overlay) ----
    float bsv[4][2];
    #pragma unroll
    for (int nt = 0; nt < 4; nt++) {
        bsv[nt][0] = sBias[p * 32 + nt * 8 + 2 * tg];
        bsv[nt][1] = sBias[p * 32 + nt * 8 + 2 * tg + 1];
    }
    __syncthreads();   // sXp dead; overlay as sRep

    // ---- repack: sRep[b*357 + o*11 + p] ----
    #pragma unroll
    for (int mt = 0; mt < 4; mt++) {
        const int b0 = mh * 64 + mt * 16 + gid;
        #pragma unroll
        for (int nt = 0; nt < 4; nt++) {
            const int o = nt * 8 + 2 * tg;
            sRep[(b0)     * 357 + (o)     * 11 + p] = acc[mt][nt][0] + bsv[nt][0];
            sRep[(b0)     * 357 + (o + 1) * 11 + p] = acc[mt][nt][1] + bsv[nt][1];
            sRep[(b0 + 8) * 357 + (o)     * 11 + p] = acc[mt][nt][2] + bsv[nt][0];
            sRep[(b0 + 8) * 357 + (o + 1) * 11 + p] = acc[mt][nt][3] + bsv[nt][1];
        }
    }
    __syncthreads();

    // ---- store: float2 over px (40B row-runs, contiguous in out) ----
    for (int j = tid; j < 4096 * 5; j += NTHR) {
        int row = j / 5;                  // b*32 + o
        int q   = j - 5 * row;            // px pair
        int b = row >> 5, o = row & 31;
        const float* rp = &sRep[b * 357 + o * 11 + 2 * q];
        float v0 = rp[0], v1 = rp[1];
        *reinterpret_cast<float2*>(&out[(size_t)row * 3600 + pos0 + 2 * q]) =
            make_float2(v0, v1);
    }
}

// ---------------------------------------------------------------- launch
extern "C" void kernel_launch(void* const* d_in, const int* in_sizes, int n_in,
                              void* d_out, int out_size)
{
    const float* x    = (const float*)d_in[0];
    const float* W    = (const float*)d_in[1];
    const float* bias = (const float*)d_in[2];
    float* out        = (float*)d_out;

    cudaFuncSetAttribute(lc2d_hmma_kernel,
                         cudaFuncAttributeMaxDynamicSharedMemorySize, SMEM_TOTAL);

    prep_x_kernel<<<dim3(8, 64, 3), dim3(32, 8)>>>(x);
    prep_w_kernel<<<3600, 256>>>(W);
    lc2d_hmma_kernel<<<dim3(RYX / TX, RYX), NTHR, SMEM_TOTAL>>>(bias, out);
}

// round 9
// speedup vs baseline: 1.0720x; 1.0720x over previous
#include <cuda_runtime.h>
#include <cuda_bf16.h>
#include <cstdint>

// Locally-connected 2D via mma.sync m16n8k16 bf16, 3-pass hi/lo split.
//   out[b,o,y,x] = sum_k patches[b,y,x,k] * W[y,x,o,k] + bias[y,x,o]
// x: [128,3,64,64] f32, W: [60,60,32,75] f32 (k = c*25+kh*5+kw),
// bias: [60,60,32] f32, out: [128,32,60,60] f32.
// CTA = (py, 8 x-positions, guarded at px>=60). warp = (p, mh).
// Stores: full aligned 32B runs per (b,o) row via swizzled smem repack.
// W fragments LDG'd directly from prepped g_wfragB with s+1 prefetch.

#define RYX  60
#define TX   8
#define XC   12          // TX + 4
#define NROW 180         // 15 * XC
#define SXB  132         // sXp row stride (u32)
#define NTHR 512

#define XP_BYTES   (NROW * SXB * 4)     // 95040 (overlaid by sRep after compute)
#define SREP_BYTES (4096 * 9 * 4)       // 147456
#define BIAS_OFF   SREP_BYTES
#define SMEM_TOTAL (BIAS_OFF + TX * 32 * 4)   // 148480

__device__ unsigned g_xp[3 * 64 * 64 * 128];   // packed x (bf16hi<<16|bf16lo), b fast
__device__ uint2    g_wfragB[3600 * 1280];     // [pos][s:5][a:2][nt:4][gid:8][tg:4]

// ---------------------------------------------------------------- helpers
__device__ __forceinline__ unsigned smem_u32(const void* p) {
    unsigned a;
    asm("{ .reg .u64 t; cvta.to.shared.u64 t, %1; cvt.u32.u64 %0, t; }" : "=r"(a) : "l"(p));
    return a;
}
__device__ __forceinline__ void cp16(unsigned sm, const void* g) {
    asm volatile("cp.async.cg.shared.global [%0], [%1], 16;"
                 :: "r"(sm), "l"(__cvta_generic_to_global(g)) : "memory");
}
__device__ __forceinline__ void cp_commit_wait() {
    asm volatile("cp.async.commit_group;" ::: "memory");
    asm volatile("cp.async.wait_group 0;" ::: "memory");
}
__device__ __forceinline__ int rcof(int k) {       // sXp row for flat k (pos 0)
    int c = k / 25, r = (k % 25) / 5, w = k % 5;
    return (c * 5 + r) * XC + w;
}
__device__ __forceinline__ void mma_bf16(float* d, const unsigned* a, unsigned b0, unsigned b1) {
    asm volatile(
        "mma.sync.aligned.m16n8k16.row.col.f32.bf16.bf16.f32 "
        "{%0,%1,%2,%3}, {%4,%5,%6,%7}, {%8,%9}, {%0,%1,%2,%3};"
        : "+f"(d[0]), "+f"(d[1]), "+f"(d[2]), "+f"(d[3])
        : "r"(a[0]), "r"(a[1]), "r"(a[2]), "r"(a[3]), "r"(b0), "r"(b1));
}

// ---------------------------------------------------------------- prep: pack x
__global__ __launch_bounds__(256)
void prep_x_kernel(const float* __restrict__ x)
{
    __shared__ unsigned tile[32][33];
    const int wt    = blockIdx.x & 1;
    const int btile = blockIdx.x >> 1;
    const int h     = blockIdx.y;
    const int c     = blockIdx.z;
    const int tx = threadIdx.x, ty = threadIdx.y;

    #pragma unroll
    for (int j = 0; j < 4; j++) {
        int b = btile * 32 + ty + j * 8;
        float v = x[(((size_t)b * 3 + c) * 64 + h) * 64 + wt * 32 + tx];
        __nv_bfloat16 hi = __float2bfloat16_rn(v);
        __nv_bfloat16 lo = __float2bfloat16_rn(v - __bfloat162float(hi));
        tile[ty + j * 8][tx] = ((unsigned)__bfloat16_as_ushort(hi) << 16)
                             |  (unsigned)__bfloat16_as_ushort(lo);
    }
    __syncthreads();
    #pragma unroll
    for (int j = 0; j < 4; j++) {
        int w = wt * 32 + ty + j * 8;
        g_xp[(((size_t)c * 64 + h) * 64 + w) * 128 + btile * 32 + tx] = tile[tx][ty + j * 8];
    }
}

// ---------------------------------------------------------------- prep: W -> B-fragment images
__global__ __launch_bounds__(256)
void prep_w_kernel(const float* __restrict__ W)
{
    const int pos = blockIdx.x;
    const float* Wg = W + (size_t)pos * (32 * 75);
    uint2* dst = g_wfragB + (size_t)pos * 1280;

    for (int i = threadIdx.x; i < 1280; i += 256) {
        int tg  = i & 3;
        int gid = (i >> 2) & 7;
        int nt  = (i >> 5) & 3;
        int a   = (i >> 7) & 1;
        int s   = i >> 8;
        int o   = nt * 8 + gid;
        int k0  = 16 * s + 2 * tg;

        float v[4];
        v[0] = (k0     < 75) ? Wg[o * 75 + k0]     : 0.0f;
        v[1] = (k0 + 1 < 75) ? Wg[o * 75 + k0 + 1] : 0.0f;
        v[2] = (k0 + 8 < 75) ? Wg[o * 75 + k0 + 8] : 0.0f;
        v[3] = (k0 + 9 < 75) ? Wg[o * 75 + k0 + 9] : 0.0f;

        unsigned r[4];
        #pragma unroll
        for (int j = 0; j < 4; j++) {
            unsigned wb = __float_as_uint(v[j]);
            if (a == 0) {
                r[j] = wb >> 16;
            } else {
                float lo = v[j] - __uint_as_float(wb & 0xFFFF0000u);
                r[j] = (unsigned)__bfloat16_as_ushort(__float2bfloat16_rn(lo));
            }
        }
        dst[i] = make_uint2(r[0] | (r[1] << 16), r[2] | (r[3] << 16));
    }
}

// ---------------------------------------------------------------- main
__global__ __launch_bounds__(NTHR, 1)
void lc2d_hmma_kernel(const float* __restrict__ bias,
                      float* __restrict__ out)
{
    extern __shared__ char smem[];
    unsigned* sXp   = (unsigned*)smem;              // [NROW][SXB] packed u32 (stage)
    float*    sRep  = (float*)smem;                 // overlay after compute: [4096][9]
    float*    sBias = (float*)(smem + BIAS_OFF);    // [TX][32]

    const int xt   = blockIdx.x;          // 0..7
    const int py   = blockIdx.y;          // 0..59
    const int px0  = xt * TX;
    const int pos0 = py * RYX + px0;
    const int tid  = threadIdx.x;

    const unsigned sXp_a = smem_u32(sXp);

    // ---- stage x tile: cp.async uint4, coalesced (col clamped at image edge) ----
    for (int i = tid; i < NROW * 32; i += NTHR) {
        int q    = i & 31;
        int rc   = i >> 5;                 // (c*5+kh)*XC + col
        int crow = rc / XC, col = rc - crow * XC;
        int c = crow / 5, kh = crow - c * 5;
        int w = px0 + col; if (w > 63) w = 63;
        cp16(sXp_a + (rc * SXB + q * 4) * 4,
             &g_xp[(((size_t)c * 64 + py + kh) * 64 + w) * 128 + q * 4]);
    }
    if (tid < TX * 32) {
        int bi = pos0 * 32 + tid;
        if (bi > 3600 * 32 - 1) bi = 3600 * 32 - 1;
        sBias[tid] = bias[bi];
    }
    cp_commit_wait();
    __syncthreads();

    // ---- compute: warp = (position p, m-half mh); 4 m-tiles x 4 n-tiles ----
    const int wid  = tid >> 5;
    const int lane = tid & 31;
    const int gid  = lane >> 2;
    const int tg   = lane & 3;
    const int p    = wid >> 1;          // 0..7
    const int mh   = wid & 1;

    float acc[4][4][4];
    #pragma unroll
    for (int mt = 0; mt < 4; mt++)
        #pragma unroll
        for (int nt = 0; nt < 4; nt++)
            #pragma unroll
            for (int r = 0; r < 4; r++) acc[mt][nt][r] = 0.0f;

    int wpos = pos0 + p; if (wpos > 3599) wpos = 3599;
    const uint2* wfp = g_wfragB + (size_t)wpos * 1280 + gid * 4 + tg;

    // prefetch s = 0 B-fragments
    uint2 bh[4], bl[4];
    #pragma unroll
    for (int nt = 0; nt < 4; nt++) {
        bh[nt] = __ldg(wfp + nt * 32);
        bl[nt] = __ldg(wfp + 128 + nt * 32);
    }

    #pragma unroll
    for (int s = 0; s < 5; s++) {
        // prefetch next s B-fragments (overlaps with this s's MMAs)
        uint2 bh2[4], bl2[4];
        if (s < 4) {
            #pragma unroll
            for (int nt = 0; nt < 4; nt++) {
                bh2[nt] = __ldg(wfp + (s + 1) * 256 + nt * 32);
                bl2[nt] = __ldg(wfp + (s + 1) * 256 + 128 + nt * 32);
            }
        }

        // A row offsets for k0, k0+1, k0+8, k0+9
        const int k0 = 16 * s + 2 * tg;
        int off0, off1, off2, off3;
        bool v2 = true, v3 = true;
        if (s < 4) {
            off0 = (rcof(k0)     + p) * SXB;
            off1 = (rcof(k0 + 1) + p) * SXB;
            off2 = (rcof(k0 + 8) + p) * SXB;
            off3 = (rcof(k0 + 9) + p) * SXB;
        } else {
            off0 = (rcof(k0)     + p) * SXB;
            off1 = (rcof(k0 + 1) + p) * SXB;
            v2 = (k0 + 8) < 75;  off2 = v2 ? (rcof(k0 + 8) + p) * SXB : 0;
            v3 = (k0 + 9) < 75;  off3 = v3 ? (rcof(k0 + 9) + p) * SXB : 0;
        }

        #pragma unroll
        for (int mt = 0; mt < 4; mt++) {
            const int b = mh * 64 + mt * 16 + gid;
            unsigned x0 = sXp[off0 + b];
            unsigned x1 = sXp[off1 + b];
            unsigned x2 = sXp[off0 + b + 8];
            unsigned x3 = sXp[off1 + b + 8];
            unsigned x4 = v2 ? sXp[off2 + b]     : 0u;
            unsigned x5 = v3 ? sXp[off3 + b]     : 0u;
            unsigned x6 = v2 ? sXp[off2 + b + 8] : 0u;
            unsigned x7 = v3 ? sXp[off3 + b + 8] : 0u;

            unsigned ah[4], al[4];
            ah[0] = __byte_perm(x0, x1, 0x7632);  al[0] = __byte_perm(x0, x1, 0x5410);
            ah[1] = __byte_perm(x2, x3, 0x7632);  al[1] = __byte_perm(x2, x3, 0x5410);
            ah[2] = __byte_perm(x4, x5, 0x7632);  al[2] = __byte_perm(x4, x5, 0x5410);
            ah[3] = __byte_perm(x6, x7, 0x7632);  al[3] = __byte_perm(x6, x7, 0x5410);

            #pragma unroll
            for (int nt = 0; nt < 4; nt++)
                mma_bf16(acc[mt][nt], ah, bh[nt].x, bh[nt].y);   // hi*hi
            #pragma unroll
            for (int nt = 0; nt < 4; nt++)
                mma_bf16(acc[mt][nt], ah, bl[nt].x, bl[nt].y);   // hi*lo
            #pragma unroll
            for (int nt = 0; nt < 4; nt++)
                mma_bf16(acc[mt][nt], al, bh[nt].x, bh[nt].y);   // lo*hi
        }

        if (s < 4) {
            #pragma unroll
            for (int nt = 0; nt < 4; nt++) { bh[nt] = bh2[nt]; bl[nt] = bl2[nt]; }
        }
    }

    // ---- bias into regs, then overlay stage with sRep ----
    float bsv[4][2];
    #pragma unroll
    for (int nt = 0; nt < 4; nt++) {
        bsv[nt][0] = sBias[p * 32 + nt * 8 + 2 * tg];
        bsv[nt][1] = sBias[p * 32 + nt * 8 + 2 * tg + 1];
    }
    __syncthreads();   // sXp dead

    // ---- repack: sRep[row*9 + ((p + b) & 7)], row = b*32 + o ----
    #pragma unroll
    for (int mt = 0; mt < 4; mt++) {
        const int b0 = mh * 64 + mt * 16 + gid;
        const int col = (p + b0) & 7;        // (p + b0 + 8) & 7 == col
        #pragma unroll
        for (int nt = 0; nt < 4; nt++) {
            const int o = nt * 8 + 2 * tg;
            sRep[((b0)     * 32 + o)     * 9 + col] = acc[mt][nt][0] + bsv[nt][0];
            sRep[((b0)     * 32 + o + 1) * 9 + col] = acc[mt][nt][1] + bsv[nt][1];
            sRep[((b0 + 8) * 32 + o)     * 9 + col] = acc[mt][nt][2] + bsv[nt][0];
            sRep[((b0 + 8) * 32 + o + 1) * 9 + col] = acc[mt][nt][3] + bsv[nt][1];
        }
    }
    __syncthreads();

    // ---- store: one thread per row, 32B aligned runs (16B on guard tile) ----
    const int vx = (px0 + TX <= RYX) ? TX : (RYX - px0);   // 8, or 4 on xt=7
    #pragma unroll
    for (int j = 0; j < 8; j++) {
        const int row = j * NTHR + tid;        // b*32 + o
        const int rot = (row >> 5) & 7;
        float v[8];
        #pragma unroll
        for (int i = 0; i < 8; i++)
            v[i] = sRep[row * 9 + ((i + rot) & 7)];
        float* op = &out[(size_t)row * 3600 + pos0];
        *reinterpret_cast<float4*>(op) = make_float4(v[0], v[1], v[2], v[3]);
        if (vx == 8)
            *reinterpret_cast<float4*>(op + 4) = make_float4(v[4], v[5], v[6], v[7]);
    }
}

// ---------------------------------------------------------------- launch
extern "C" void kernel_launch(void* const* d_in, const int* in_sizes, int n_in,
                              void* d_out, int out_size)
{
    const float* x    = (const float*)d_in[0];
    const float* W    = (const float*)d_in[1];
    const float* bias = (const float*)d_in[2];
    float* out        = (float*)d_out;

    cudaFuncSetAttribute(lc2d_hmma_kernel,
                         cudaFuncAttributeMaxDynamicSharedMemorySize, SMEM_TOTAL);

    prep_x_kernel<<<dim3(8, 64, 3), dim3(32, 8)>>>(x);
    prep_w_kernel<<<3600, 256>>>(W);
    lc2d_hmma_kernel<<<dim3(TX, RYX), NTHR, SMEM_TOTAL>>>(bias, out);
}

// round 10
// speedup vs baseline: 1.3077x; 1.2199x over previous
#include <cuda_runtime.h>
#include <cuda_fp16.h>
#include <cstdint>

// Locally-connected 2D via single-pass fp16 mma.sync m16n8k16.
//   out[b,o,y,x] = sum_k patches[b,y,x,k] * W[y,x,o,k] + bias[y,x,o]
// x: [128,3,64,64] f32, W: [60,60,32,75] f32 (k = c*25+kh*5+kw),
// bias: [60,60,32] f32, out: [128,32,60,60] f32.
// Per position: D[128x32] = A[128x75] @ B[75x32], fp16 inputs, fp32 accum.
// prep_ap builds A-fragment pair-planes g_ap[kp][h][w][b] (fp16(k)|fp16(k+1))
// so each A-register is a single conflict-free LDS.32. prep_w builds per-warp
// coalesced B-fragment images. Repack + float4 store identical to R5.

#define RYX  60
#define TX   4
#define NTHR 256
#define SAS  520          // sA per-kp stride in u32 (4*128 + 8 pad)

#define SA_BYTES   (40 * SAS * 4)          // 83200
#define BIAS_OFF   SA_BYTES
#define SMEM_TOTAL (BIAS_OFF + 512)        // 83712

__device__ float    g_xT[3 * 64 * 64 * 128];      // x transposed [c][h][w][b]
__device__ unsigned g_ap[40 * 64 * 64 * 128];     // pair-planes [kp][h][w][b]
__device__ uint2    g_wf[3600 * 640];             // [pos][s:5][nt:4][gid:8][tg:4]

// ---------------------------------------------------------------- helpers
__device__ __forceinline__ unsigned smem_u32(const void* p) {
    unsigned a;
    asm("{ .reg .u64 t; cvta.to.shared.u64 t, %1; cvt.u32.u64 %0, t; }" : "=r"(a) : "l"(p));
    return a;
}
__device__ __forceinline__ void cp16(unsigned sm, const void* g) {
    asm volatile("cp.async.cg.shared.global [%0], [%1], 16;"
                 :: "r"(sm), "l"(__cvta_generic_to_global(g)) : "memory");
}
__device__ __forceinline__ void cp_commit_wait() {
    asm volatile("cp.async.commit_group;" ::: "memory");
    asm volatile("cp.async.wait_group 0;" ::: "memory");
}
__device__ __forceinline__ void mma_f16(float* d, const unsigned* a, unsigned b0, unsigned b1) {
    asm volatile(
        "mma.sync.aligned.m16n8k16.row.col.f32.f16.f16.f32 "
        "{%0,%1,%2,%3}, {%4,%5,%6,%7}, {%8,%9}, {%0,%1,%2,%3};"
        : "+f"(d[0]), "+f"(d[1]), "+f"(d[2]), "+f"(d[3])
        : "r"(a[0]), "r"(a[1]), "r"(a[2]), "r"(a[3]), "r"(b0), "r"(b1));
}
__device__ __forceinline__ void kcrd(int k, int& c, int& r, int& w) {
    c = k / 25; int rem = k - c * 25; r = rem / 5; w = rem - r * 5;
}

// ---------------------------------------------------------------- prep 1: transpose x
__global__ __launch_bounds__(256)
void transpose_x_kernel(const float* __restrict__ x)
{
    __shared__ float tile[32][33];
    const int wt    = blockIdx.x & 1;
    const int btile = blockIdx.x >> 1;
    const int h     = blockIdx.y;
    const int c     = blockIdx.z;
    const int tx = threadIdx.x, ty = threadIdx.y;

    #pragma unroll
    for (int j = 0; j < 4; j++) {
        int b = btile * 32 + ty + j * 8;
        tile[ty + j * 8][tx] =
            x[(((size_t)b * 3 + c) * 64 + h) * 64 + wt * 32 + tx];
    }
    __syncthreads();
    #pragma unroll
    for (int j = 0; j < 4; j++) {
        int w = wt * 32 + ty + j * 8;
        g_xT[(((size_t)c * 64 + h) * 64 + w) * 128 + btile * 32 + tx] =
            tile[tx][ty + j * 8];
    }
}

// ---------------------------------------------------------------- prep 2: pair-planes
// g_ap[kp][hh][ww][b] = fp16(x[c0, hh, ww, b]) | fp16(x[c1, hh+dh, ww+dw, b]) << 16
// where k0 = 2kp (element 0 coords c0,r0,kw0; plane indexed by e0's coords) and
// k1 = k0+1 gives (c1,r1,kw1), dh = r1-r0, dw = kw1-kw0. Zero for k >= 75.
__global__ __launch_bounds__(256)
void prep_ap_kernel()
{
    const int kp = blockIdx.x;     // 0..39
    const int hh = blockIdx.y;     // 0..63
    const int k0 = 2 * kp, k1 = k0 + 1;
    const bool v0 = (k0 < 75), v1 = (k1 < 75);

    int c0, r0, w0, c1, r1, w1;
    kcrd(k0, c0, r0, w0);
    kcrd(k1, c1, r1, w1);
    int h1 = hh + (r1 - r0); if (h1 < 0) h1 = 0; if (h1 > 63) h1 = 63;
    const int dw = w1 - w0;

    unsigned* dst = g_ap + ((size_t)(kp * 64 + hh) * 64) * 128;

    for (int i = threadIdx.x; i < 2048; i += 256) {    // 64 ww x 32 b-quads
        int ww = i >> 5;
        int bq = (i & 31) * 4;
        int wwe = ww + dw; if (wwe < 0) wwe = 0; if (wwe > 63) wwe = 63;

        float4 e0 = make_float4(0.f, 0.f, 0.f, 0.f);
        float4 e1 = e0;
        if (v0) e0 = *reinterpret_cast<const float4*>(
                     &g_xT[((size_t)(c0 * 64 + hh) * 64 + ww) * 128 + bq]);
        if (v1) e1 = *reinterpret_cast<const float4*>(
                     &g_xT[((size_t)(c1 * 64 + h1) * 64 + wwe) * 128 + bq]);

        uint4 o;
        o.x = (unsigned)__half_as_ushort(__float2half_rn(e0.x))
            | ((unsigned)__half_as_ushort(__float2half_rn(e1.x)) << 16);
        o.y = (unsigned)__half_as_ushort(__float2half_rn(e0.y))
            | ((unsigned)__half_as_ushort(__float2half_rn(e1.y)) << 16);
        o.z = (unsigned)__half_as_ushort(__float2half_rn(e0.z))
            | ((unsigned)__half_as_ushort(__float2half_rn(e1.z)) << 16);
        o.w = (unsigned)__half_as_ushort(__float2half_rn(e0.w))
            | ((unsigned)__half_as_ushort(__float2half_rn(e1.w)) << 16);
        *reinterpret_cast<uint4*>(&dst[(size_t)ww * 128 + bq]) = o;
    }
}

// ---------------------------------------------------------------- prep 3: W fragments
// uint2 at [pos][s][nt][gid][tg]: o = nt*8+gid, k0 = 16s+2tg
//   .x = fp16(W[o,k0])   | fp16(W[o,k0+1]) << 16
//   .y = fp16(W[o,k0+8]) | fp16(W[o,k0+9]) << 16      (zero for k >= 75)
__global__ __launch_bounds__(256)
void prep_w_kernel(const float* __restrict__ W)
{
    const int pos = blockIdx.x;
    const float* Wg = W + (size_t)pos * (32 * 75);
    uint2* dst = g_wf + (size_t)pos * 640;

    for (int i = threadIdx.x; i < 640; i += 256) {
        int tg  = i & 3;
        int gid = (i >> 2) & 7;
        int nt  = (i >> 5) & 3;
        int s   = i >> 7;
        int o   = nt * 8 + gid;
        int k0  = 16 * s + 2 * tg;

        unsigned r[4];
        #pragma unroll
        for (int j = 0; j < 4; j++) {
            int k = k0 + (j >> 1) * 8 + (j & 1);
            float v = (k < 75) ? Wg[o * 75 + k] : 0.0f;
            r[j] = (unsigned)__half_as_ushort(__float2half_rn(v));
        }
        dst[i] = make_uint2(r[0] | (r[1] << 16), r[2] | (r[3] << 16));
    }
}

// ---------------------------------------------------------------- main
__global__ __launch_bounds__(NTHR, 2)
void lc2d_hmma_kernel(const float* __restrict__ bias,
                      float* __restrict__ out)
{
    extern __shared__ char smem[];
    unsigned* sA    = (unsigned*)smem;              // [40 kp][SAS]
    float*    sBias = (float*)(smem + BIAS_OFF);    // [TX][32]

    const int xt   = blockIdx.x;          // 15
    const int py   = blockIdx.y;          // 60
    const int px0  = xt * TX;
    const int pos0 = py * RYX + px0;
    const int tid  = threadIdx.x;

    const unsigned sA_a = smem_u32(sA);

    // ---- stage A pair-planes: 40 kp x 512 u32 contiguous, cp.async ----
    for (int i = tid; i < 40 * 128; i += NTHR) {
        int kp = i >> 7;
        int q  = i & 127;
        int c0, r0, w0;
        kcrd(2 * kp, c0, r0, w0);
        cp16(sA_a + (kp * SAS + q * 4) * 4,
             &g_ap[((size_t)(kp * 64 + py + r0) * 64 + px0 + w0) * 128 + q * 4]);
    }
    if (tid < TX * 32) sBias[tid] = bias[pos0 * 32 + tid];
    cp_commit_wait();
    __syncthreads();

    // ---- compute: warp = (position p, m-half mh); 4 m-tiles x 4 n-tiles ----
    const int wid  = tid >> 5;
    const int lane = tid & 31;
    const int gid  = lane >> 2;
    const int tg   = lane & 3;
    const int p    = wid >> 1;          // 0..3
    const int mh   = wid & 1;

    float acc[4][4][4];
    #pragma unroll
    for (int mt = 0; mt < 4; mt++)
        #pragma unroll
        for (int nt = 0; nt < 4; nt++)
            #pragma unroll
            for (int r = 0; r < 4; r++) acc[mt][nt][r] = 0.0f;

    const uint2* wfp = g_wf + (size_t)(pos0 + p) * 640 + gid * 4 + tg;

    // prefetch s = 0 B-fragments
    uint2 bh[4];
    #pragma unroll
    for (int nt = 0; nt < 4; nt++) bh[nt] = __ldg(wfp + nt * 32);

    #pragma unroll
    for (int s = 0; s < 5; s++) {
        uint2 bh2[4];
        if (s < 4) {
            #pragma unroll
            for (int nt = 0; nt < 4; nt++)
                bh2[nt] = __ldg(wfp + (s + 1) * 128 + nt * 32);
        }

        const int base0 = (8 * s + tg) * SAS + p * 128;       // k-pair (k0, k0+1)
        const int base1 = (8 * s + 4 + tg) * SAS + p * 128;   // k-pair (k0+8, k0+9)

        #pragma unroll
        for (int mt = 0; mt < 4; mt++) {
            const int b = mh * 64 + mt * 16 + gid;
            unsigned a[4];
            a[0] = sA[base0 + b];
            a[1] = sA[base0 + b + 8];
            a[2] = sA[base1 + b];
            a[3] = sA[base1 + b + 8];

            #pragma unroll
            for (int nt = 0; nt < 4; nt++)
                mma_f16(acc[mt][nt], a, bh[nt].x, bh[nt].y);
        }

        if (s < 4) {
            #pragma unroll
            for (int nt = 0; nt < 4; nt++) bh[nt] = bh2[nt];
        }
    }

    // ---- bias into regs, then overlay sA with repack buffer ----
    float bsv[4][2];
    #pragma unroll
    for (int nt = 0; nt < 4; nt++) {
        bsv[nt][0] = sBias[p * 32 + nt * 8 + 2 * tg];
        bsv[nt][1] = sBias[p * 32 + nt * 8 + 2 * tg + 1];
    }
    __syncthreads();   // sA dead

    // ---- repack: sRep[px][b][o-pair] float2 ----
    float2* sRep = (float2*)smem;        // [(p*128 + b)*17 + nt*4 + tg]
    #pragma unroll
    for (int mt = 0; mt < 4; mt++) {
        #pragma unroll
        for (int rh = 0; rh < 2; rh++) {
            const int b = mh * 64 + mt * 16 + gid + rh * 8;
            #pragma unroll
            for (int nt = 0; nt < 4; nt++) {
                sRep[(p * 128 + b) * 17 + nt * 4 + tg] =
                    make_float2(acc[mt][nt][rh * 2] + bsv[nt][0],
                                acc[mt][nt][rh * 2 + 1] + bsv[nt][1]);
            }
        }
    }
    __syncthreads();

    // ---- store: float4 over px (16B contiguous) ----
    const float* rf = (const float*)smem;
    for (int j = tid; j < 128 * 32; j += NTHR) {
        int b = j >> 5, o = j & 31;
        float4 v;
        v.x = rf[((0 * 128 + b) * 34) + o];
        v.y = rf[((1 * 128 + b) * 34) + o];
        v.z = rf[((2 * 128 + b) * 34) + o];
        v.w = rf[((3 * 128 + b) * 34) + o];
        *reinterpret_cast<float4*>(&out[((size_t)(b * 32 + o)) * 3600 + pos0]) = v;
    }
}

// ---------------------------------------------------------------- launch
extern "C" void kernel_launch(void* const* d_in, const int* in_sizes, int n_in,
                              void* d_out, int out_size)
{
    const float* x    = (const float*)d_in[0];
    const float* W    = (const float*)d_in[1];
    const float* bias = (const float*)d_in[2];
    float* out        = (float*)d_out;

    cudaFuncSetAttribute(lc2d_hmma_kernel,
                         cudaFuncAttributeMaxDynamicSharedMemorySize, SMEM_TOTAL);

    transpose_x_kernel<<<dim3(8, 64, 3), dim3(32, 8)>>>(x);
    prep_ap_kernel<<<dim3(40, 64), 256>>>();
    prep_w_kernel<<<3600, 256>>>(W);
    lc2d_hmma_kernel<<<dim3(RYX / TX, RYX), NTHR, SMEM_TOTAL>>>(bias, out);
}

// round 11
// speedup vs baseline: 1.8714x; 1.4311x over previous
#include <cuda_runtime.h>
#include <cuda_fp16.h>
#include <cstdint>

// Locally-connected 2D via single-pass fp16 mma.sync m16n8k16.
//   out[b,o,y,x] = sum_k patches[b,y,x,k] * W[y,x,o,k] + bias[y,x,o]
// x: [128,3,64,64] f32, W: [60,60,32,75] f32 (k = c*25+kh*5+kw),
// bias: [60,60,32] f32, out: [128,32,60,60] f32.
// Per position: D[128x32] = A[128x75] @ B[75x32], fp16 inputs, fp32 accum.
// x stored compact as fp16 g_xh[c][h][w][b] (3.1MB, L2-resident); A-registers
// built in-loop from two LDS.U16 (bank-verified conflict-free). W pre-split
// into per-warp coalesced fragment images (g_wf). Repack + float4 store = R10.

#define RYX  60
#define TX   4
#define NTHR 256
#define SXS  136          // sXh row stride in u16 (128 + 8 pad)

#define SREP_BYTES 69632                   // sRep overlay (8704 float2)
#define BIAS_OFF   SREP_BYTES
#define SMEM_TOTAL (BIAS_OFF + 512)        // 70144

__device__ unsigned short g_xh[3 * 64 * 64 * 128];   // fp16 x, [c][h][w][b]
__device__ uint2          g_wf[3600 * 640];          // [pos][s:5][nt:4][gid:8][tg:4]

// ---------------------------------------------------------------- helpers
__device__ __forceinline__ unsigned smem_u32(const void* p) {
    unsigned a;
    asm("{ .reg .u64 t; cvta.to.shared.u64 t, %1; cvt.u32.u64 %0, t; }" : "=r"(a) : "l"(p));
    return a;
}
__device__ __forceinline__ void cp16(unsigned sm, const void* g) {
    asm volatile("cp.async.cg.shared.global [%0], [%1], 16;"
                 :: "r"(sm), "l"(__cvta_generic_to_global(g)) : "memory");
}
__device__ __forceinline__ void cp_commit_wait() {
    asm volatile("cp.async.commit_group;" ::: "memory");
    asm volatile("cp.async.wait_group 0;" ::: "memory");
}
__device__ __forceinline__ int rcof(int k) {       // sXh row for flat k (pos 0)
    int c = k / 25, r = (k % 25) / 5, w = k % 5;
    return (c * 5 + r) * 8 + w;
}
__device__ __forceinline__ void mma_f16(float* d, const unsigned* a, unsigned b0, unsigned b1) {
    asm volatile(
        "mma.sync.aligned.m16n8k16.row.col.f32.f16.f16.f32 "
        "{%0,%1,%2,%3}, {%4,%5,%6,%7}, {%8,%9}, {%0,%1,%2,%3};"
        : "+f"(d[0]), "+f"(d[1]), "+f"(d[2]), "+f"(d[3])
        : "r"(a[0]), "r"(a[1]), "r"(a[2]), "r"(a[3]), "r"(b0), "r"(b1));
}

// ---------------------------------------------------------------- prep 1: x -> fp16 [c][h][w][b]
__global__ __launch_bounds__(256)
void prep_xh_kernel(const float* __restrict__ x)
{
    __shared__ float tile[32][33];
    const int wt    = blockIdx.x & 1;
    const int btile = blockIdx.x >> 1;
    const int h     = blockIdx.y;
    const int c     = blockIdx.z;
    const int tx = threadIdx.x, ty = threadIdx.y;

    #pragma unroll
    for (int j = 0; j < 4; j++) {
        int b = btile * 32 + ty + j * 8;
        tile[ty + j * 8][tx] =
            x[(((size_t)b * 3 + c) * 64 + h) * 64 + wt * 32 + tx];
    }
    __syncthreads();
    #pragma unroll
    for (int j = 0; j < 4; j++) {
        int w = wt * 32 + ty + j * 8;
        g_xh[(((size_t)c * 64 + h) * 64 + w) * 128 + btile * 32 + tx] =
            __half_as_ushort(__float2half_rn(tile[tx][ty + j * 8]));
    }
}

// ---------------------------------------------------------------- prep 2: W fragments
// uint2 at [pos][s][nt][gid][tg]: o = nt*8+gid, k0 = 16s+2tg
//   .x = fp16(W[o,k0])   | fp16(W[o,k0+1]) << 16
//   .y = fp16(W[o,k0+8]) | fp16(W[o,k0+9]) << 16      (zero for k >= 75)
__global__ __launch_bounds__(256)
void prep_w_kernel(const float* __restrict__ W)
{
    const int pos = blockIdx.x;
    const float* Wg = W + (size_t)pos * (32 * 75);
    uint2* dst = g_wf + (size_t)pos * 640;

    for (int i = threadIdx.x; i < 640; i += 256) {
        int tg  = i & 3;
        int gid = (i >> 2) & 7;
        int nt  = (i >> 5) & 3;
        int s   = i >> 7;
        int o   = nt * 8 + gid;
        int k0  = 16 * s + 2 * tg;

        unsigned r[4];
        #pragma unroll
        for (int j = 0; j < 4; j++) {
            int k = k0 + (j >> 1) * 8 + (j & 1);
            float v = (k < 75) ? Wg[o * 75 + k] : 0.0f;
            r[j] = (unsigned)__half_as_ushort(__float2half_rn(v));
        }
        dst[i] = make_uint2(r[0] | (r[1] << 16), r[2] | (r[3] << 16));
    }
}

// ---------------------------------------------------------------- main
__global__ __launch_bounds__(NTHR, 2)
void lc2d_hmma_kernel(const float* __restrict__ bias,
                      float* __restrict__ out)
{
    extern __shared__ char smem[];
    unsigned short* sXh = (unsigned short*)smem;     // [120 rows][SXS]
    float* sBias = (float*)(smem + BIAS_OFF);        // [TX][32]

    const int xt   = blockIdx.x;          // 15
    const int py   = blockIdx.y;          // 60
    const int px0  = xt * TX;
    const int pos0 = py * RYX + px0;
    const int tid  = threadIdx.x;

    const unsigned sXh_a = smem_u32(sXh);

    // ---- stage x tile: 120 rows x 128 u16, cp.async 16B chunks ----
    for (int i = tid; i < 120 * 16; i += NTHR) {
        int q    = i & 15;
        int rc   = i >> 4;                 // (c*5+kh)*8 + col
        int crow = rc >> 3, col = rc & 7;
        int c = crow / 5, kh = crow - c * 5;
        cp16(sXh_a + (rc * SXS + q * 8) * 2,
             &g_xh[(((size_t)c * 64 + py + kh) * 64 + px0 + col) * 128 + q * 8]);
    }
    if (tid < TX * 32) sBias[tid] = bias[pos0 * 32 + tid];
    cp_commit_wait();
    __syncthreads();

    // ---- compute: warp = (position p, m-half mh); 4 m-tiles x 4 n-tiles ----
    const int wid  = tid >> 5;
    const int lane = tid & 31;
    const int gid  = lane >> 2;
    const int tg   = lane & 3;
    const int p    = wid >> 1;          // 0..3
    const int mh   = wid & 1;

    float acc[4][4][4];
    #pragma unroll
    for (int mt = 0; mt < 4; mt++)
        #pragma unroll
        for (int nt = 0; nt < 4; nt++)
            #pragma unroll
            for (int r = 0; r < 4; r++) acc[mt][nt][r] = 0.0f;

    const uint2* wfp = g_wf + (size_t)(pos0 + p) * 640 + gid * 4 + tg;

    // prefetch s = 0 B-fragments
    uint2 bh[4];
    #pragma unroll
    for (int nt = 0; nt < 4; nt++) bh[nt] = __ldg(wfp + nt * 32);

    #pragma unroll
    for (int s = 0; s < 5; s++) {
        uint2 bh2[4];
        if (s < 4) {
            #pragma unroll
            for (int nt = 0; nt < 4; nt++)
                bh2[nt] = __ldg(wfp + (s + 1) * 128 + nt * 32);
        }

        // A row offsets (u16 index) for k0, k0+1, k0+8, k0+9
        const int k0 = 16 * s + 2 * tg;
        const int off00 = (rcof(k0)     + p) * SXS;
        const int off01 = (rcof(k0 + 1) + p) * SXS;
        const bool v2 = (k0 + 8) < 75;
        const bool v3 = (k0 + 9) < 75;
        const int off10 = v2 ? (rcof(k0 + 8) + p) * SXS : 0;
        const int off11 = v3 ? (rcof(k0 + 9) + p) * SXS : 0;

        #pragma unroll
        for (int mt = 0; mt < 4; mt++) {
            const int b = mh * 64 + mt * 16 + gid;
            unsigned a[4];
            a[0] = (unsigned)sXh[off00 + b]
                 | ((unsigned)sXh[off01 + b] << 16);
            a[1] = (unsigned)sXh[off00 + b + 8]
                 | ((unsigned)sXh[off01 + b + 8] << 16);
            a[2] = (v2 ? (unsigned)sXh[off10 + b] : 0u)
                 | ((v3 ? (unsigned)sXh[off11 + b] : 0u) << 16);
            a[3] = (v2 ? (unsigned)sXh[off10 + b + 8] : 0u)
                 | ((v3 ? (unsigned)sXh[off11 + b + 8] : 0u) << 16);

            #pragma unroll
            for (int nt = 0; nt < 4; nt++)
                mma_f16(acc[mt][nt], a, bh[nt].x, bh[nt].y);
        }

        if (s < 4) {
            #pragma unroll
            for (int nt = 0; nt < 4; nt++) bh[nt] = bh2[nt];
        }
    }

    // ---- bias into regs, then overlay stage with repack buffer ----
    float bsv[4][2];
    #pragma unroll
    for (int nt = 0; nt < 4; nt++) {
        bsv[nt][0] = sBias[p * 32 + nt * 8 + 2 * tg];
        bsv[nt][1] = sBias[p * 32 + nt * 8 + 2 * tg + 1];
    }
    __syncthreads();   // sXh dead

    // ---- repack: sRep[px][b][o-pair] float2 ----
    float2* sRep = (float2*)smem;        // [(p*128 + b)*17 + nt*4 + tg]
    #pragma unroll
    for (int mt = 0; mt < 4; mt++) {
        #pragma unroll
        for (int rh = 0; rh < 2; rh++) {
            const int b = mh * 64 + mt * 16 + gid + rh * 8;
            #pragma unroll
            for (int nt = 0; nt < 4; nt++) {
                sRep[(p * 128 + b) * 17 + nt * 4 + tg] =
                    make_float2(acc[mt][nt][rh * 2] + bsv[nt][0],
                                acc[mt][nt][rh * 2 + 1] + bsv[nt][1]);
            }
        }
    }
    __syncthreads();

    // ---- store: float4 over px (16B contiguous) ----
    const float* rf = (const float*)smem;
    for (int j = tid; j < 128 * 32; j += NTHR) {
        int b = j >> 5, o = j & 31;
        float4 v;
        v.x = rf[((0 * 128 + b) * 34) + o];
        v.y = rf[((1 * 128 + b) * 34) + o];
        v.z = rf[((2 * 128 + b) * 34) + o];
        v.w = rf[((3 * 128 + b) * 34) + o];
        *reinterpret_cast<float4*>(&out[((size_t)(b * 32 + o)) * 3600 + pos0]) = v;
    }
}

// ---------------------------------------------------------------- launch
extern "C" void kernel_launch(void* const* d_in, const int* in_sizes, int n_in,
                              void* d_out, int out_size)
{
    const float* x    = (const float*)d_in[0];
    const float* W    = (const float*)d_in[1];
    const float* bias = (const float*)d_in[2];
    float* out        = (float*)d_out;

    cudaFuncSetAttribute(lc2d_hmma_kernel,
                         cudaFuncAttributeMaxDynamicSharedMemorySize, SMEM_TOTAL);

    prep_xh_kernel<<<dim3(8, 64, 3), dim3(32, 8)>>>(x);
    prep_w_kernel<<<3600, 256>>>(W);
    lc2d_hmma_kernel<<<dim3(RYX / TX, RYX), NTHR, SMEM_TOTAL>>>(bias, out);
}